// round 2
// baseline (speedup 1.0000x reference)
#include <cuda_runtime.h>
#include <cstdint>

// YoloLayer: x (64, 30, 152, 152) f32 -> out (64, 3*152*152, 10) f32
// Vectorized: 4 positions/thread, float4 loads, smem-staged float4 stores.

#define G     152
#define GG    (G * G)            // 23104, divisible by 4
#define A     3
#define F     10
#define B     64
#define BLK   256
#define VEC   4
#define POS_PER_BLK (BLK * VEC)  // 1024
#define PAD   44                 // padded floats per thread region (11 float4, 12-bank stride)

__constant__ float c_anchor_w[A] = {12.0f, 19.0f, 40.0f};
__constant__ float c_anchor_h[A] = {16.0f, 36.0f, 28.0f};

__device__ __forceinline__ float fsigmoid(float v) {
    return 1.0f / (1.0f + __expf(-v));
}

__global__ __launch_bounds__(BLK) void yolo_kernel(
    const float* __restrict__ x,
    const int*   __restrict__ img,
    float*       __restrict__ out)
{
    __shared__ float s[BLK * PAD];   // 45056 B

    const int tid = threadIdx.x;
    const int p0  = (blockIdx.x * BLK + tid) * VEC;  // base position, multiple of 4

    // Decode img_size (int32 or f32 bits)
    int iv = img[0];
    float img_f = (iv > 0 && iv < 1000000) ? (float)iv : __int_as_float(iv);
    const float stride = img_f / (float)G;           // 8.0

    // p0 -> (b, a, sidx); all 4 positions share b, a, yy (G % 4 == 0)
    const int b    = p0 / (A * GG);
    int rem        = p0 - b * (A * GG);
    const int a    = rem / GG;
    const int sidx = rem - a * GG;
    const int yy   = sidx / G;
    const int xx0  = sidx - yy * G;

    const float* base = x + ((size_t)(b * (A * F) + a * F)) * GG + sidx;

    // 10 independent 128-bit loads
    float4 v[F];
#pragma unroll
    for (int f = 0; f < F; f++)
        v[f] = *(const float4*)(base + (size_t)f * GG);

    const float SXY = 1.05f;
    const float OFF = 0.025f;
    const float aw  = c_anchor_w[a];
    const float ah  = c_anchor_h[a];
    const float fy  = (float)yy;

    // Results in output order: ro[j*10 + f] for position j
    float ro[VEC * F];
#pragma unroll
    for (int j = 0; j < VEC; j++) {
        const float vx[F] = { ((const float*)&v[0])[j], ((const float*)&v[1])[j],
                              ((const float*)&v[2])[j], ((const float*)&v[3])[j],
                              ((const float*)&v[4])[j], ((const float*)&v[5])[j],
                              ((const float*)&v[6])[j], ((const float*)&v[7])[j],
                              ((const float*)&v[8])[j], ((const float*)&v[9])[j] };
        ro[j*F + 0] = (fsigmoid(vx[0]) * SXY - OFF + (float)(xx0 + j)) * stride;
        ro[j*F + 1] = (fsigmoid(vx[1]) * SXY - OFF + fy) * stride;
        ro[j*F + 2] = __expf(vx[2]) * aw;
        ro[j*F + 3] = __expf(vx[3]) * ah;
        ro[j*F + 4] = vx[4];
        ro[j*F + 5] = vx[5];
        ro[j*F + 6] = fsigmoid(vx[6]);
        ro[j*F + 7] = fsigmoid(vx[7]);
        ro[j*F + 8] = fsigmoid(vx[8]);
        ro[j*F + 9] = fsigmoid(vx[9]);
    }

    // Stage to smem: 10 STS.128, stride 44 floats => conflict-free phases
    float4* sv = (float4*)(s + tid * PAD);
#pragma unroll
    for (int i = 0; i < F; i++)
        sv[i] = make_float4(ro[4*i+0], ro[4*i+1], ro[4*i+2], ro[4*i+3]);

    __syncthreads();

    // Coalesced readout: block slice = 10240 contiguous floats = 2560 float4
    float4* ob = (float4*)(out + (size_t)blockIdx.x * (POS_PER_BLK * F));
    const float4* sf = (const float4*)s;
#pragma unroll
    for (int k = 0; k < F; k++) {
        int Lf   = tid + k * BLK;        // logical float4 index in output slice
        int own  = Lf / F;               // owning thread
        int off  = Lf - own * F;         // float4 offset within its 40 floats
        float4 val = sf[own * (PAD/4) + off];
        __stcs(&ob[Lf], val);            // streaming store, evict-first
    }
}

extern "C" void kernel_launch(void* const* d_in, const int* in_sizes, int n_in,
                              void* d_out, int out_size)
{
    const float* x   = (const float*)d_in[0];
    const int*   img = (n_in >= 2) ? (const int*)d_in[1] : nullptr;
    float*       out = (float*)d_out;

    const int total = B * A * GG;             // 4,435,968
    const int grid  = total / POS_PER_BLK;    // 4332 exactly

    yolo_kernel<<<grid, BLK>>>(x, img, out);
}

// round 3
// speedup vs baseline: 1.1176x; 1.1176x over previous
#include <cuda_runtime.h>
#include <cstdint>

// YoloLayer: x (64, 30, 152, 152) f32 -> out (64, 3*152*152, 10) f32
// VEC=2: float2 loads (LDG.64), 2 positions/thread, 20KB smem staging,
// STG.128 coalesced output. Lean registers to keep occupancy high.

#define G     152
#define GG    (G * G)            // 23104, even
#define A     3
#define F     10
#define B     64
#define BLK   256
#define VEC   2
#define POS_PER_BLK (BLK * VEC)  // 512

__constant__ float c_anchor_w[A] = {12.0f, 19.0f, 40.0f};
__constant__ float c_anchor_h[A] = {16.0f, 36.0f, 28.0f};

__device__ __forceinline__ float fsigmoid(float v) {
    return 1.0f / (1.0f + __expf(-v));
}

__global__ __launch_bounds__(BLK) void yolo_kernel(
    const float* __restrict__ x,
    const int*   __restrict__ img,
    float*       __restrict__ out)
{
    __shared__ float s[POS_PER_BLK * F];     // 20480 B

    const int tid = threadIdx.x;
    const int p0  = (blockIdx.x * BLK + tid) * VEC;   // even position

    int iv = img[0];
    float img_f = (iv > 0 && iv < 1000000) ? (float)iv : __int_as_float(iv);
    const float stride = img_f / (float)G;            // 8.0

    // Both positions share b, a, yy (G even, GG even)
    const int b    = p0 / (A * GG);
    int rem        = p0 - b * (A * GG);
    const int a    = rem / GG;
    const int sidx = rem - a * GG;
    const int yy   = sidx / G;
    const int xx0  = sidx - yy * G;

    const float* base = x + ((size_t)(b * (A * F) + a * F)) * GG + sidx;

    // 10 independent LDG.64
    float2 v[F];
#pragma unroll
    for (int f = 0; f < F; f++)
        v[f] = *(const float2*)(base + (size_t)f * GG);

    const float SXY = 1.05f;
    const float OFF = 0.025f;
    const float aw  = c_anchor_w[a];
    const float ah  = c_anchor_h[a];
    const float fy  = (float)yy;

    // Compute + stage per position sequentially (limits live registers)
    float* sp = s + tid * (VEC * F);
#pragma unroll
    for (int j = 0; j < VEC; j++) {
        float r0 = (fsigmoid(j ? v[0].y : v[0].x) * SXY - OFF + (float)(xx0 + j)) * stride;
        float r1 = (fsigmoid(j ? v[1].y : v[1].x) * SXY - OFF + fy) * stride;
        float r2 = __expf(j ? v[2].y : v[2].x) * aw;
        float r3 = __expf(j ? v[3].y : v[3].x) * ah;
        // STS.128 x2 + ... write as float4 pairs: [r0..r3], [r4..r7], [r8,r9 | next]
        ((float4*)(sp + j * F))[0] = make_float4(r0, r1, r2, r3);
        float r4 = j ? v[4].y : v[4].x;
        float r5 = j ? v[5].y : v[5].x;
        float r6 = fsigmoid(j ? v[6].y : v[6].x);
        float r7 = fsigmoid(j ? v[7].y : v[7].x);
        ((float4*)(sp + j * F))[1] = make_float4(r4, r5, r6, r7);
        float r8 = fsigmoid(j ? v[8].y : v[8].x);
        float r9 = fsigmoid(j ? v[9].y : v[9].x);
        ((float2*)(sp + j * F))[4] = make_float2(r8, r9);
    }

    __syncthreads();

    // Block output slice: 512*10 = 5120 contiguous floats = 1280 float4.
    // 5 fully-coalesced STG.128 per thread.
    float4* ob = (float4*)(out + (size_t)blockIdx.x * (POS_PER_BLK * F));
    const float4* sf = (const float4*)s;
#pragma unroll
    for (int jj = 0; jj < 5; jj++)
        ob[tid + jj * BLK] = sf[tid + jj * BLK];
}

extern "C" void kernel_launch(void* const* d_in, const int* in_sizes, int n_in,
                              void* d_out, int out_size)
{
    const float* x   = (const float*)d_in[0];
    const int*   img = (n_in >= 2) ? (const int*)d_in[1] : nullptr;
    float*       out = (float*)d_out;

    const int total = B * A * GG;             // 4,435,968
    const int grid  = total / POS_PER_BLK;    // 8664 exactly

    yolo_kernel<<<grid, BLK>>>(x, img, out);
}